// round 3
// baseline (speedup 1.0000x reference)
#include <cuda_runtime.h>
#include <cuda_bf16.h>
#include <math.h>

// Problem constants
#define B_  2
#define T_  2048
#define E_  2048
#define HQ_ 32
#define HKV_ 8
#define HD_ 64
#define KVD_ (HKV_ * HD_)   // 512
#define M_  (B_ * T_)       // 4096

// Scratch (device globals — no allocation allowed)
__device__ float g_Q[(size_t)M_ * E_];    // [B*T, HQ*HD]
__device__ float g_K[(size_t)M_ * KVD_];  // [B*T, HKV*HD]
__device__ float g_V[(size_t)M_ * KVD_];  // [B*T, HKV*HD]
__device__ float g_A[(size_t)M_ * E_];    // attention output [B*T, HQ*HD]

// ---------------------------------------------------------------------------
// Tiled SGEMM: C[M,N] = A[M,K] @ B[K,N] (+bias). 64x64 tile, BK=16,
// 256 threads, 4x4 per-thread register blocking, float4 SMEM reads.
// All dims divisible by tiles (M=4096, N in {512,2048}, K=2048).
// ---------------------------------------------------------------------------
__global__ __launch_bounds__(256) void sgemm_kernel(
    const float* __restrict__ A, const float* __restrict__ Bm,
    float* __restrict__ C, int M, int N, int K,
    const float* __restrict__ bias)
{
    __shared__ float As[16][64];  // k-major
    __shared__ float Bs[16][64];

    const int tid = threadIdx.x;
    const int tx = tid & 15;
    const int ty = tid >> 4;
    const int row0 = blockIdx.y * 64;
    const int col0 = blockIdx.x * 64;

    float acc[4][4] = {};

    const int ar = tid >> 2;        // 0..63
    const int ac = (tid & 3) * 4;   // 0,4,8,12
    const int br = tid >> 4;        // 0..15
    const int bc = (tid & 15) * 4;  // 0..60

    const float* Aptr = A + (size_t)(row0 + ar) * K + ac;
    const float* Bptr = Bm + (size_t)br * N + col0 + bc;

    for (int k0 = 0; k0 < K; k0 += 16) {
        float4 av = *reinterpret_cast<const float4*>(Aptr + k0);
        float4 bv = *reinterpret_cast<const float4*>(Bptr + (size_t)k0 * N);
        As[ac + 0][ar] = av.x;
        As[ac + 1][ar] = av.y;
        As[ac + 2][ar] = av.z;
        As[ac + 3][ar] = av.w;
        *reinterpret_cast<float4*>(&Bs[br][bc]) = bv;
        __syncthreads();

#pragma unroll
        for (int k = 0; k < 16; k++) {
            float4 a4 = *reinterpret_cast<const float4*>(&As[k][ty * 4]);
            float4 b4 = *reinterpret_cast<const float4*>(&Bs[k][tx * 4]);
            float a[4] = {a4.x, a4.y, a4.z, a4.w};
            float b[4] = {b4.x, b4.y, b4.z, b4.w};
#pragma unroll
            for (int i = 0; i < 4; i++)
#pragma unroll
                for (int j = 0; j < 4; j++)
                    acc[i][j] = fmaf(a[i], b[j], acc[i][j]);
        }
        __syncthreads();
    }

    float4 bb = make_float4(0.f, 0.f, 0.f, 0.f);
    if (bias) bb = *reinterpret_cast<const float4*>(&bias[col0 + tx * 4]);

#pragma unroll
    for (int i = 0; i < 4; i++) {
        int r = row0 + ty * 4 + i;
        float4 o;
        o.x = acc[i][0] + bb.x;
        o.y = acc[i][1] + bb.y;
        o.z = acc[i][2] + bb.z;
        o.w = acc[i][3] + bb.w;
        *reinterpret_cast<float4*>(&C[(size_t)r * N + col0 + tx * 4]) = o;
    }
}

// ---------------------------------------------------------------------------
// Flash attention: one block = 64 queries x one query head x one batch.
// Online softmax over 32 key tiles of 64. 256 threads, 4x4 register blocking.
// SMEM rows padded to 65 floats -> <=2-way bank conflicts on all patterns.
// ---------------------------------------------------------------------------
__global__ __launch_bounds__(256) void attn_kernel(
    const float* __restrict__ Q, const float* __restrict__ K,
    const float* __restrict__ V, float* __restrict__ O)
{
    __shared__ float Qs[64][65];
    __shared__ float Ks[64][65];  // reused as P after S is computed
    __shared__ float Vs[64][65];

    const int tid = threadIdx.x;
    const int tx = tid & 15;
    const int ty = tid >> 4;
    const int q0 = blockIdx.x * 64;
    const int hq = blockIdx.y;
    const int b  = blockIdx.z;
    const int hkv = hq >> 2;  // GROUP = 4
    const float scale = 0.125f;  // 1/sqrt(64)

    // Load Q tile (scaled). 64 rows x 64 cols, 4 float4 per thread, coalesced.
#pragma unroll
    for (int i = 0; i < 4; i++) {
        int lin = tid + i * 256;
        int r = lin >> 4;
        int c = (lin & 15) * 4;
        float4 v = *reinterpret_cast<const float4*>(
            &Q[(size_t)(b * T_ + q0 + r) * E_ + hq * HD_ + c]);
        Qs[r][c + 0] = v.x * scale;
        Qs[r][c + 1] = v.y * scale;
        Qs[r][c + 2] = v.z * scale;
        Qs[r][c + 3] = v.w * scale;
    }

    float m[4], l[4], o[4][4];
#pragma unroll
    for (int i = 0; i < 4; i++) {
        m[i] = -INFINITY;
        l[i] = 0.f;
#pragma unroll
        for (int c = 0; c < 4; c++) o[i][c] = 0.f;
    }

    for (int kt = 0; kt < T_; kt += 64) {
        // Load K and V tiles (64x64 each), coalesced.
#pragma unroll
        for (int i = 0; i < 4; i++) {
            int lin = tid + i * 256;
            int r = lin >> 4;
            int c = (lin & 15) * 4;
            size_t base = (size_t)(b * T_ + kt + r) * KVD_ + hkv * HD_ + c;
            float4 kv = *reinterpret_cast<const float4*>(&K[base]);
            float4 vv = *reinterpret_cast<const float4*>(&V[base]);
            Ks[r][c + 0] = kv.x; Ks[r][c + 1] = kv.y;
            Ks[r][c + 2] = kv.z; Ks[r][c + 3] = kv.w;
            Vs[r][c + 0] = vv.x; Vs[r][c + 1] = vv.y;
            Vs[r][c + 2] = vv.z; Vs[r][c + 3] = vv.w;
        }
        __syncthreads();

        // S = Qs @ Ks^T (scaled already). 4x4 per thread.
        float p[4][4] = {};
#pragma unroll 8
        for (int d = 0; d < 64; d++) {
            float a[4], bb[4];
#pragma unroll
            for (int i = 0; i < 4; i++) a[i] = Qs[ty * 4 + i][d];
#pragma unroll
            for (int j = 0; j < 4; j++) bb[j] = Ks[tx * 4 + j][d];
#pragma unroll
            for (int i = 0; i < 4; i++)
#pragma unroll
                for (int j = 0; j < 4; j++)
                    p[i][j] = fmaf(a[i], bb[j], p[i][j]);
        }

        // Online softmax per row (row split across 16 tx lanes).
#pragma unroll
        for (int i = 0; i < 4; i++) {
            float rm = fmaxf(fmaxf(p[i][0], p[i][1]), fmaxf(p[i][2], p[i][3]));
#pragma unroll
            for (int off = 1; off < 16; off <<= 1)
                rm = fmaxf(rm, __shfl_xor_sync(0xffffffffu, rm, off));
            float mn = fmaxf(m[i], rm);
            float corr = __expf(m[i] - mn);
            float rs = 0.f;
#pragma unroll
            for (int j = 0; j < 4; j++) {
                p[i][j] = __expf(p[i][j] - mn);
                rs += p[i][j];
            }
#pragma unroll
            for (int off = 1; off < 16; off <<= 1)
                rs += __shfl_xor_sync(0xffffffffu, rs, off);
            l[i] = l[i] * corr + rs;
            m[i] = mn;
#pragma unroll
            for (int c = 0; c < 4; c++) o[i][c] *= corr;
        }

        __syncthreads();  // everyone done reading Ks before overwrite with P

        // Store P into Ks (as Ps[q][j])
#pragma unroll
        for (int i = 0; i < 4; i++)
#pragma unroll
            for (int j = 0; j < 4; j++)
                Ks[ty * 4 + i][tx * 4 + j] = p[i][j];
        __syncthreads();

        // O += P @ V
#pragma unroll 8
        for (int j = 0; j < 64; j++) {
            float pv[4], vv[4];
#pragma unroll
            for (int i = 0; i < 4; i++) pv[i] = Ks[ty * 4 + i][j];
#pragma unroll
            for (int c = 0; c < 4; c++) vv[c] = Vs[j][tx * 4 + c];
#pragma unroll
            for (int i = 0; i < 4; i++)
#pragma unroll
                for (int c = 0; c < 4; c++)
                    o[i][c] = fmaf(pv[i], vv[c], o[i][c]);
        }
        __syncthreads();  // before next tile overwrites Ks/Vs
    }

    // Epilogue: normalize and write [B*T, HQ*HD]
#pragma unroll
    for (int i = 0; i < 4; i++) {
        float inv = 1.f / l[i];
        int r = b * T_ + q0 + ty * 4 + i;
        float4 ov;
        ov.x = o[i][0] * inv;
        ov.y = o[i][1] * inv;
        ov.z = o[i][2] * inv;
        ov.w = o[i][3] * inv;
        *reinterpret_cast<float4*>(&g_A[(size_t)r * E_ + hq * HD_ + tx * 4]) = ov;
    }
}

// ---------------------------------------------------------------------------
extern "C" void kernel_launch(void* const* d_in, const int* in_sizes, int n_in,
                              void* d_out, int out_size)
{
    const float* x  = (const float*)d_in[0];
    const float* Wq = (const float*)d_in[1];
    const float* Wk = (const float*)d_in[2];
    const float* Wv = (const float*)d_in[3];
    const float* Wo = (const float*)d_in[4];
    const float* bo = (const float*)d_in[5];
    float* out = (float*)d_out;

    float *pQ, *pK, *pV, *pA;
    cudaGetSymbolAddress((void**)&pQ, g_Q);
    cudaGetSymbolAddress((void**)&pK, g_K);
    cudaGetSymbolAddress((void**)&pV, g_V);
    cudaGetSymbolAddress((void**)&pA, g_A);

    dim3 blk(256);

    // Q = x @ Wq   [4096 x 2048]
    sgemm_kernel<<<dim3(E_ / 64, M_ / 64), blk>>>(x, Wq, pQ, M_, E_, E_, nullptr);
    // K = x @ Wk   [4096 x 512]
    sgemm_kernel<<<dim3(KVD_ / 64, M_ / 64), blk>>>(x, Wk, pK, M_, KVD_, E_, nullptr);
    // V = x @ Wv   [4096 x 512]
    sgemm_kernel<<<dim3(KVD_ / 64, M_ / 64), blk>>>(x, Wv, pV, M_, KVD_, E_, nullptr);

    // Attention
    attn_kernel<<<dim3(T_ / 64, HQ_, B_), blk>>>(pQ, pK, pV, pA);

    // out = attn @ Wo + bo   [4096 x 2048]
    sgemm_kernel<<<dim3(E_ / 64, M_ / 64), blk>>>(pA, Wo, out, M_, E_, E_, bo);
}

// round 4
// speedup vs baseline: 1.0003x; 1.0003x over previous
#include <cuda_runtime.h>
#include <cuda_bf16.h>
#include <math.h>

// Problem constants
#define B_  2
#define T_  2048
#define E_  2048
#define HQ_ 32
#define HKV_ 8
#define HD_ 64
#define KVD_ (HKV_ * HD_)   // 512
#define M_  (B_ * T_)       // 4096

// Scratch (device globals — no allocation allowed)
__device__ float g_Q[(size_t)M_ * E_];    // [B*T, HQ*HD]
__device__ float g_K[(size_t)M_ * KVD_];  // [B*T, HKV*HD]
__device__ float g_V[(size_t)M_ * KVD_];  // [B*T, HKV*HD]
__device__ float g_A[(size_t)M_ * E_];    // attention output [B*T, HQ*HD]

// ---------------------------------------------------------------------------
// Tiled SGEMM: C[M,N] = A[M,K] @ B[K,N] (+bias). 64x64 tile, BK=16,
// 256 threads, 4x4 per-thread register blocking, float4 SMEM reads.
// All dims divisible by tiles (M=4096, N in {512,2048}, K=2048).
// ---------------------------------------------------------------------------
__global__ __launch_bounds__(256) void sgemm_kernel(
    const float* __restrict__ A, const float* __restrict__ Bm,
    float* __restrict__ C, int M, int N, int K,
    const float* __restrict__ bias)
{
    __shared__ float As[16][64];  // k-major
    __shared__ float Bs[16][64];

    const int tid = threadIdx.x;
    const int tx = tid & 15;
    const int ty = tid >> 4;
    const int row0 = blockIdx.y * 64;
    const int col0 = blockIdx.x * 64;

    float acc[4][4] = {};

    const int ar = tid >> 2;        // 0..63
    const int ac = (tid & 3) * 4;   // 0,4,8,12
    const int br = tid >> 4;        // 0..15
    const int bc = (tid & 15) * 4;  // 0..60

    const float* Aptr = A + (size_t)(row0 + ar) * K + ac;
    const float* Bptr = Bm + (size_t)br * N + col0 + bc;

    for (int k0 = 0; k0 < K; k0 += 16) {
        float4 av = *reinterpret_cast<const float4*>(Aptr + k0);
        float4 bv = *reinterpret_cast<const float4*>(Bptr + (size_t)k0 * N);
        As[ac + 0][ar] = av.x;
        As[ac + 1][ar] = av.y;
        As[ac + 2][ar] = av.z;
        As[ac + 3][ar] = av.w;
        *reinterpret_cast<float4*>(&Bs[br][bc]) = bv;
        __syncthreads();

#pragma unroll
        for (int k = 0; k < 16; k++) {
            float4 a4 = *reinterpret_cast<const float4*>(&As[k][ty * 4]);
            float4 b4 = *reinterpret_cast<const float4*>(&Bs[k][tx * 4]);
            float a[4] = {a4.x, a4.y, a4.z, a4.w};
            float b[4] = {b4.x, b4.y, b4.z, b4.w};
#pragma unroll
            for (int i = 0; i < 4; i++)
#pragma unroll
                for (int j = 0; j < 4; j++)
                    acc[i][j] = fmaf(a[i], b[j], acc[i][j]);
        }
        __syncthreads();
    }

    float4 bb = make_float4(0.f, 0.f, 0.f, 0.f);
    if (bias) bb = *reinterpret_cast<const float4*>(&bias[col0 + tx * 4]);

#pragma unroll
    for (int i = 0; i < 4; i++) {
        int r = row0 + ty * 4 + i;
        float4 o;
        o.x = acc[i][0] + bb.x;
        o.y = acc[i][1] + bb.y;
        o.z = acc[i][2] + bb.z;
        o.w = acc[i][3] + bb.w;
        *reinterpret_cast<float4*>(&C[(size_t)r * N + col0 + tx * 4]) = o;
    }
}

// ---------------------------------------------------------------------------
// Flash attention: one block = 64 queries x one query head x one batch.
// Online softmax over 32 key tiles of 64. 256 threads, 4x4 register blocking.
// SMEM rows padded to 65 floats -> <=2-way bank conflicts on all patterns.
// ---------------------------------------------------------------------------
__global__ __launch_bounds__(256) void attn_kernel(
    const float* __restrict__ Q, const float* __restrict__ K,
    const float* __restrict__ V, float* __restrict__ O)
{
    __shared__ float Qs[64][65];
    __shared__ float Ks[64][65];  // reused as P after S is computed
    __shared__ float Vs[64][65];

    const int tid = threadIdx.x;
    const int tx = tid & 15;
    const int ty = tid >> 4;
    const int q0 = blockIdx.x * 64;
    const int hq = blockIdx.y;
    const int b  = blockIdx.z;
    const int hkv = hq >> 2;  // GROUP = 4
    const float scale = 0.125f;  // 1/sqrt(64)

    // Load Q tile (scaled). 64 rows x 64 cols, 4 float4 per thread, coalesced.
#pragma unroll
    for (int i = 0; i < 4; i++) {
        int lin = tid + i * 256;
        int r = lin >> 4;
        int c = (lin & 15) * 4;
        float4 v = *reinterpret_cast<const float4*>(
            &Q[(size_t)(b * T_ + q0 + r) * E_ + hq * HD_ + c]);
        Qs[r][c + 0] = v.x * scale;
        Qs[r][c + 1] = v.y * scale;
        Qs[r][c + 2] = v.z * scale;
        Qs[r][c + 3] = v.w * scale;
    }

    float m[4], l[4], o[4][4];
#pragma unroll
    for (int i = 0; i < 4; i++) {
        m[i] = -INFINITY;
        l[i] = 0.f;
#pragma unroll
        for (int c = 0; c < 4; c++) o[i][c] = 0.f;
    }

    for (int kt = 0; kt < T_; kt += 64) {
        // Load K and V tiles (64x64 each), coalesced.
#pragma unroll
        for (int i = 0; i < 4; i++) {
            int lin = tid + i * 256;
            int r = lin >> 4;
            int c = (lin & 15) * 4;
            size_t base = (size_t)(b * T_ + kt + r) * KVD_ + hkv * HD_ + c;
            float4 kv = *reinterpret_cast<const float4*>(&K[base]);
            float4 vv = *reinterpret_cast<const float4*>(&V[base]);
            Ks[r][c + 0] = kv.x; Ks[r][c + 1] = kv.y;
            Ks[r][c + 2] = kv.z; Ks[r][c + 3] = kv.w;
            Vs[r][c + 0] = vv.x; Vs[r][c + 1] = vv.y;
            Vs[r][c + 2] = vv.z; Vs[r][c + 3] = vv.w;
        }
        __syncthreads();

        // S = Qs @ Ks^T (scaled already). 4x4 per thread.
        float p[4][4] = {};
#pragma unroll 8
        for (int d = 0; d < 64; d++) {
            float a[4], bb[4];
#pragma unroll
            for (int i = 0; i < 4; i++) a[i] = Qs[ty * 4 + i][d];
#pragma unroll
            for (int j = 0; j < 4; j++) bb[j] = Ks[tx * 4 + j][d];
#pragma unroll
            for (int i = 0; i < 4; i++)
#pragma unroll
                for (int j = 0; j < 4; j++)
                    p[i][j] = fmaf(a[i], bb[j], p[i][j]);
        }

        // Online softmax per row (row split across 16 tx lanes).
#pragma unroll
        for (int i = 0; i < 4; i++) {
            float rm = fmaxf(fmaxf(p[i][0], p[i][1]), fmaxf(p[i][2], p[i][3]));
#pragma unroll
            for (int off = 1; off < 16; off <<= 1)
                rm = fmaxf(rm, __shfl_xor_sync(0xffffffffu, rm, off));
            float mn = fmaxf(m[i], rm);
            float corr = __expf(m[i] - mn);
            float rs = 0.f;
#pragma unroll
            for (int j = 0; j < 4; j++) {
                p[i][j] = __expf(p[i][j] - mn);
                rs += p[i][j];
            }
#pragma unroll
            for (int off = 1; off < 16; off <<= 1)
                rs += __shfl_xor_sync(0xffffffffu, rs, off);
            l[i] = l[i] * corr + rs;
            m[i] = mn;
#pragma unroll
            for (int c = 0; c < 4; c++) o[i][c] *= corr;
        }

        __syncthreads();  // everyone done reading Ks before overwrite with P

        // Store P into Ks (as Ps[q][j])
#pragma unroll
        for (int i = 0; i < 4; i++)
#pragma unroll
            for (int j = 0; j < 4; j++)
                Ks[ty * 4 + i][tx * 4 + j] = p[i][j];
        __syncthreads();

        // O += P @ V
#pragma unroll 8
        for (int j = 0; j < 64; j++) {
            float pv[4], vv[4];
#pragma unroll
            for (int i = 0; i < 4; i++) pv[i] = Ks[ty * 4 + i][j];
#pragma unroll
            for (int c = 0; c < 4; c++) vv[c] = Vs[j][tx * 4 + c];
#pragma unroll
            for (int i = 0; i < 4; i++)
#pragma unroll
                for (int c = 0; c < 4; c++)
                    o[i][c] = fmaf(pv[i], vv[c], o[i][c]);
        }
        __syncthreads();  // before next tile overwrites Ks/Vs
    }

    // Epilogue: normalize and write [B*T, HQ*HD]
#pragma unroll
    for (int i = 0; i < 4; i++) {
        float inv = 1.f / l[i];
        int r = b * T_ + q0 + ty * 4 + i;
        float4 ov;
        ov.x = o[i][0] * inv;
        ov.y = o[i][1] * inv;
        ov.z = o[i][2] * inv;
        ov.w = o[i][3] * inv;
        *reinterpret_cast<float4*>(&g_A[(size_t)r * E_ + hq * HD_ + tx * 4]) = ov;
    }
}

// ---------------------------------------------------------------------------
extern "C" void kernel_launch(void* const* d_in, const int* in_sizes, int n_in,
                              void* d_out, int out_size)
{
    const float* x  = (const float*)d_in[0];
    const float* Wq = (const float*)d_in[1];
    const float* Wk = (const float*)d_in[2];
    const float* Wv = (const float*)d_in[3];
    const float* Wo = (const float*)d_in[4];
    const float* bo = (const float*)d_in[5];
    float* out = (float*)d_out;

    float *pQ, *pK, *pV, *pA;
    cudaGetSymbolAddress((void**)&pQ, g_Q);
    cudaGetSymbolAddress((void**)&pK, g_K);
    cudaGetSymbolAddress((void**)&pV, g_V);
    cudaGetSymbolAddress((void**)&pA, g_A);

    dim3 blk(256);

    // Q = x @ Wq   [4096 x 2048]
    sgemm_kernel<<<dim3(E_ / 64, M_ / 64), blk>>>(x, Wq, pQ, M_, E_, E_, nullptr);
    // K = x @ Wk   [4096 x 512]
    sgemm_kernel<<<dim3(KVD_ / 64, M_ / 64), blk>>>(x, Wk, pK, M_, KVD_, E_, nullptr);
    // V = x @ Wv   [4096 x 512]
    sgemm_kernel<<<dim3(KVD_ / 64, M_ / 64), blk>>>(x, Wv, pV, M_, KVD_, E_, nullptr);

    // Attention
    attn_kernel<<<dim3(T_ / 64, HQ_, B_), blk>>>(pQ, pK, pV, pA);

    // out = attn @ Wo + bo   [4096 x 2048]
    sgemm_kernel<<<dim3(E_ / 64, M_ / 64), blk>>>(pA, Wo, out, M_, E_, E_, bo);
}

// round 6
// speedup vs baseline: 2.6508x; 2.6499x over previous
#include <cuda_runtime.h>
#include <cuda_bf16.h>
#include <math.h>
#include <stdint.h>

#define B_   2
#define T_   2048
#define E_   2048
#define HQ_  32
#define HKV_ 8
#define HD_  64
#define KVD_ 512
#define M_   4096
#define NH_  64   // B_*HQ_

typedef __nv_bfloat16 bf16;

// ---------------------------------------------------------------------------
// Device scratch (globals: no runtime allocation)
// ---------------------------------------------------------------------------
__device__ bf16 g_xh[(size_t)M_*E_],   g_xl[(size_t)M_*E_];
__device__ bf16 g_Wqh[(size_t)E_*E_],  g_Wql[(size_t)E_*E_];     // Wq^T [E,E]
__device__ bf16 g_Wkh[(size_t)KVD_*E_],g_Wkl[(size_t)KVD_*E_];   // Wk^T [512,2048]
__device__ bf16 g_Wvh[(size_t)KVD_*E_],g_Wvl[(size_t)KVD_*E_];   // Wv^T
__device__ bf16 g_Woh[(size_t)E_*E_],  g_Wol[(size_t)E_*E_];     // Wo^T
__device__ bf16 g_Qh[(size_t)M_*E_],   g_Ql[(size_t)M_*E_];      // Q*0.125
__device__ bf16 g_Kh[(size_t)M_*KVD_], g_Kl[(size_t)M_*KVD_];
__device__ bf16 g_Vth[(size_t)KVD_*M_],g_Vtl[(size_t)KVD_*M_];   // V^T [512,4096]
__device__ float g_S[(size_t)NH_*T_*T_];                          // 1 GB
__device__ bf16 g_Ph[(size_t)NH_*T_*T_], g_Pl[(size_t)NH_*T_*T_];
__device__ bf16 g_Ah[(size_t)M_*E_],   g_Al[(size_t)M_*E_];

// ---------------------------------------------------------------------------
// Helpers
// ---------------------------------------------------------------------------
__device__ __forceinline__ uint32_t smem_u32(const void* p) {
    return (uint32_t)__cvta_generic_to_shared(p);
}
#define CP_ASYNC16(sa, ga) \
    asm volatile("cp.async.cg.shared.global [%0], [%1], 16;" :: "r"(sa), "l"(ga))
#define CP_COMMIT() asm volatile("cp.async.commit_group;" ::: "memory")
#define CP_WAIT0()  asm volatile("cp.async.wait_group 0;" ::: "memory")
#define CP_WAIT1()  asm volatile("cp.async.wait_group 1;" ::: "memory")

__device__ __forceinline__ void ldm_x4(uint32_t* r, uint32_t addr) {
    asm volatile("ldmatrix.sync.aligned.m8n8.x4.shared.b16 {%0,%1,%2,%3}, [%4];"
        : "=r"(r[0]), "=r"(r[1]), "=r"(r[2]), "=r"(r[3]) : "r"(addr));
}
__device__ __forceinline__ void ldm_x2(uint32_t* r, uint32_t addr) {
    asm volatile("ldmatrix.sync.aligned.m8n8.x2.shared.b16 {%0,%1}, [%2];"
        : "=r"(r[0]), "=r"(r[1]) : "r"(addr));
}
__device__ __forceinline__ void mma16816(float* c, const uint32_t* a, const uint32_t* b) {
    asm volatile("mma.sync.aligned.m16n8k16.row.col.f32.bf16.bf16.f32 "
        "{%0,%1,%2,%3}, {%4,%5,%6,%7}, {%8,%9}, {%0,%1,%2,%3};"
        : "+f"(c[0]), "+f"(c[1]), "+f"(c[2]), "+f"(c[3])
        : "r"(a[0]), "r"(a[1]), "r"(a[2]), "r"(a[3]), "r"(b[0]), "r"(b[1]));
}
__device__ __forceinline__ void split2(float v, bf16& h, bf16& l) {
    h = __float2bfloat16(v);
    l = __float2bfloat16(v - __bfloat162float(h));
}
__device__ __forceinline__ uint32_t pack2(float a, float b) {
    bf16 x = __float2bfloat16(a), y = __float2bfloat16(b);
    return (uint32_t)__bfloat16_as_ushort(x) | ((uint32_t)__bfloat16_as_ushort(y) << 16);
}

// Stage loader: ROWS x 32 bf16 tile -> SMEM rows padded to 80B, via cp.async
template<int ROWS>
__device__ __forceinline__ void stage_load(uint32_t sdst, const bf16* __restrict__ g,
                                           int ld, int tid) {
#pragma unroll
    for (int i = 0; i < ROWS / 64; i++) {
        int idx = tid + i * 256;
        int r = idx >> 2, q = idx & 3;
        CP_ASYNC16(sdst + r * 80 + q * 16, g + (size_t)r * ld + q * 8);
    }
}

// ---------------------------------------------------------------------------
// Warp-MMA GEMM, hi/lo bf16 split (3 HMMA per product term).
// D[m][n] = sum_k A[m][k]*B[n][k]; A,B row-major K-major (B is [N,K]).
// CTA tile 128 x BN, BK=32, 8 warps (2x4), warp tile 64 x BN/4.
// OUT=0: fp32 +bias.  OUT=1: hi/lo bf16 *scale.
// blockIdx.z = b*32+hq for batched attention GEMMs.
// ---------------------------------------------------------------------------
template<int BN, int OUT>
__global__ __launch_bounds__(256) void gemm_mma(
    const bf16* __restrict__ Ah_, const bf16* __restrict__ Al_,
    const bf16* __restrict__ Bh_, const bf16* __restrict__ Bl_,
    int lda, int ldb, int nk,
    long long aSB, long long aSH, long long bSB, long long bSH,
    long long cSB, long long cSH,
    float* Cf, const float* bias, bf16* Ch, bf16* Cl, int ldc, float scale)
{
    extern __shared__ char smem[];
    const uint32_t sb = smem_u32(smem);
    const int tid = threadIdx.x, wid = tid >> 5, lane = tid & 31;
    const int wm = wid & 1, wn = wid >> 1;   // 2 x 4 warp grid
    constexpr int WN = BN / 4;               // warp N extent
    constexpr int NT = WN / 8;               // n-tiles per warp
    constexpr int ATB = 128 * 80;            // 10240 B per A tile
    constexpr int BTB = BN * 80;             // B tile bytes
    constexpr int STG = 2 * ATB + 2 * BTB;   // stage bytes

    const int z = blockIdx.z, b = z >> 5, hq = z & 31;
    const long long aOff = (long long)b * aSB + (long long)hq * aSH;
    const long long bOff = (long long)b * bSB + (long long)(hq >> 2) * bSH;
    const long long cOff = (long long)b * cSB + (long long)hq * cSH;

    const int row0 = blockIdx.y * 128;
    const int col0 = blockIdx.x * BN;

    const bf16* gAh = Ah_ + aOff + (size_t)row0 * lda;
    const bf16* gAl = Al_ + aOff + (size_t)row0 * lda;
    const bf16* gBh = Bh_ + bOff + (size_t)col0 * ldb;
    const bf16* gBl = Bl_ + bOff + (size_t)col0 * ldb;

    float acc[4][NT][4];
#pragma unroll
    for (int i = 0; i < 4; i++)
#pragma unroll
        for (int j = 0; j < NT; j++)
#pragma unroll
            for (int c = 0; c < 4; c++) acc[i][j][c] = 0.f;

    // prologue: stage 0
    stage_load<128>(sb,                 gAh, lda, tid);
    stage_load<128>(sb + ATB,           gAl, lda, tid);
    stage_load<BN >(sb + 2 * ATB,       gBh, ldb, tid);
    stage_load<BN >(sb + 2 * ATB + BTB, gBl, ldb, tid);
    CP_COMMIT();

    // per-lane ldmatrix address bases (byte offsets within a stage)
    const uint32_t aRow = (uint32_t)(wm * 64 + (lane & 15)) * 80 + (lane >> 4) * 16;
    const uint32_t bRow = (uint32_t)(wn * WN + (lane & 7)) * 80 + ((lane >> 3) & 1) * 16;

    for (int kt = 0; kt < nk; kt++) {
        const int cur = kt & 1;
        if (kt + 1 < nk) {
            const int nxt = (kt + 1) & 1;
            const uint32_t sn = sb + nxt * STG;
            stage_load<128>(sn,                 gAh + (kt + 1) * 32, lda, tid);
            stage_load<128>(sn + ATB,           gAl + (kt + 1) * 32, lda, tid);
            stage_load<BN >(sn + 2 * ATB,       gBh + (kt + 1) * 32, ldb, tid);
            stage_load<BN >(sn + 2 * ATB + BTB, gBl + (kt + 1) * 32, ldb, tid);
            CP_COMMIT();
            CP_WAIT1();
        } else {
            CP_WAIT0();
        }
        __syncthreads();

        const uint32_t sa = sb + cur * STG + aRow;
        const uint32_t sbv = sb + cur * STG + 2 * ATB + bRow;
#pragma unroll
        for (int ks = 0; ks < 2; ks++) {
            uint32_t ah[4][4], al[4][4], bh[NT][2], bl[NT][2];
#pragma unroll
            for (int mt = 0; mt < 4; mt++) {
                ldm_x4(ah[mt], sa + mt * 16 * 80 + ks * 32);
                ldm_x4(al[mt], sa + ATB + mt * 16 * 80 + ks * 32);
            }
#pragma unroll
            for (int nt = 0; nt < NT; nt++) {
                ldm_x2(bh[nt], sbv + nt * 8 * 80 + ks * 32);
                ldm_x2(bl[nt], sbv + BTB + nt * 8 * 80 + ks * 32);
            }
#pragma unroll
            for (int mt = 0; mt < 4; mt++)
#pragma unroll
                for (int nt = 0; nt < NT; nt++) {
                    mma16816(acc[mt][nt], ah[mt], bh[nt]);
                    mma16816(acc[mt][nt], ah[mt], bl[nt]);
                    mma16816(acc[mt][nt], al[mt], bh[nt]);
                }
        }
        __syncthreads();
    }

    // epilogue
    const int rw = lane >> 2, cw = (lane & 3) * 2;
#pragma unroll
    for (int mt = 0; mt < 4; mt++) {
#pragma unroll
        for (int nt = 0; nt < NT; nt++) {
            const int rg = row0 + wm * 64 + mt * 16 + rw;
            const int cg = col0 + wn * WN + nt * 8 + cw;
            float v0 = acc[mt][nt][0], v1 = acc[mt][nt][1];
            float v2 = acc[mt][nt][2], v3 = acc[mt][nt][3];
            if (OUT == 0) {
                float b0 = 0.f, b1 = 0.f;
                if (bias) { b0 = bias[cg]; b1 = bias[cg + 1]; }
                float2 u0 = make_float2(v0 + b0, v1 + b1);
                float2 u1 = make_float2(v2 + b0, v3 + b1);
                *reinterpret_cast<float2*>(Cf + cOff + (size_t)rg * ldc + cg) = u0;
                *reinterpret_cast<float2*>(Cf + cOff + (size_t)(rg + 8) * ldc + cg) = u1;
            } else {
                v0 *= scale; v1 *= scale; v2 *= scale; v3 *= scale;
                bf16 h0, l0, h1, l1, h2, l2, h3, l3;
                split2(v0, h0, l0); split2(v1, h1, l1);
                split2(v2, h2, l2); split2(v3, h3, l3);
                size_t i0 = cOff + (size_t)rg * ldc + cg;
                size_t i1 = cOff + (size_t)(rg + 8) * ldc + cg;
                *reinterpret_cast<uint32_t*>(Ch + i0) =
                    (uint32_t)__bfloat16_as_ushort(h0) | ((uint32_t)__bfloat16_as_ushort(h1) << 16);
                *reinterpret_cast<uint32_t*>(Cl + i0) =
                    (uint32_t)__bfloat16_as_ushort(l0) | ((uint32_t)__bfloat16_as_ushort(l1) << 16);
                *reinterpret_cast<uint32_t*>(Ch + i1) =
                    (uint32_t)__bfloat16_as_ushort(h2) | ((uint32_t)__bfloat16_as_ushort(h3) << 16);
                *reinterpret_cast<uint32_t*>(Cl + i1) =
                    (uint32_t)__bfloat16_as_ushort(l2) | ((uint32_t)__bfloat16_as_ushort(l3) << 16);
            }
        }
    }
}

// ---------------------------------------------------------------------------
// Transpose + split: W[K,N] fp32 -> Th/Tl [N,K] bf16
// ---------------------------------------------------------------------------
__global__ void tsplit_kernel(const float* __restrict__ W, bf16* __restrict__ Th,
                              bf16* __restrict__ Tl, int K, int N)
{
    __shared__ float s[32][33];
    int n0 = blockIdx.x * 32, k0 = blockIdx.y * 32;
    int tx = threadIdx.x, ty = threadIdx.y;
#pragma unroll
    for (int i = ty; i < 32; i += 8)
        s[i][tx] = W[(size_t)(k0 + i) * N + n0 + tx];
    __syncthreads();
#pragma unroll
    for (int i = ty; i < 32; i += 8) {
        float v = s[tx][i];
        bf16 h, l; split2(v, h, l);
        Th[(size_t)(n0 + i) * K + k0 + tx] = h;
        Tl[(size_t)(n0 + i) * K + k0 + tx] = l;
    }
}

__global__ void split_kernel(const float* __restrict__ x, bf16* __restrict__ xh,
                             bf16* __restrict__ xl)
{
    size_t i = (size_t)blockIdx.x * blockDim.x + threadIdx.x;
    float4 v = reinterpret_cast<const float4*>(x)[i];
    bf16 h0, l0, h1, l1, h2, l2, h3, l3;
    split2(v.x, h0, l0); split2(v.y, h1, l1);
    split2(v.z, h2, l2); split2(v.w, h3, l3);
    uint2 hv, lv;
    hv.x = __bfloat16_as_ushort(h0) | ((uint32_t)__bfloat16_as_ushort(h1) << 16);
    hv.y = __bfloat16_as_ushort(h2) | ((uint32_t)__bfloat16_as_ushort(h3) << 16);
    lv.x = __bfloat16_as_ushort(l0) | ((uint32_t)__bfloat16_as_ushort(l1) << 16);
    lv.y = __bfloat16_as_ushort(l2) | ((uint32_t)__bfloat16_as_ushort(l3) << 16);
    reinterpret_cast<uint2*>(xh)[i] = hv;
    reinterpret_cast<uint2*>(xl)[i] = lv;
}

// ---------------------------------------------------------------------------
// Row softmax: S row (2048 fp32) -> P hi/lo bf16
// ---------------------------------------------------------------------------
__global__ __launch_bounds__(256) void softmax_kernel(
    const float* __restrict__ S, bf16* __restrict__ Ph, bf16* __restrict__ Pl)
{
    __shared__ float red[8];
    const size_t row = blockIdx.x;
    const float* sr = S + row * T_;
    const int tid = threadIdx.x, wid = tid >> 5, lane = tid & 31;

    float v[8];
#pragma unroll
    for (int i = 0; i < 2; i++) {
        float4 f = reinterpret_cast<const float4*>(sr)[tid + i * 256];
        v[i * 4 + 0] = f.x; v[i * 4 + 1] = f.y; v[i * 4 + 2] = f.z; v[i * 4 + 3] = f.w;
    }
    float mx = v[0];
#pragma unroll
    for (int i = 1; i < 8; i++) mx = fmaxf(mx, v[i]);
#pragma unroll
    for (int o = 16; o > 0; o >>= 1) mx = fmaxf(mx, __shfl_xor_sync(~0u, mx, o));
    if (lane == 0) red[wid] = mx;
    __syncthreads();
    mx = red[0];
#pragma unroll
    for (int i = 1; i < 8; i++) mx = fmaxf(mx, red[i]);
    __syncthreads();

    float sum = 0.f;
#pragma unroll
    for (int i = 0; i < 8; i++) { v[i] = __expf(v[i] - mx); sum += v[i]; }
#pragma unroll
    for (int o = 16; o > 0; o >>= 1) sum += __shfl_xor_sync(~0u, sum, o);
    if (lane == 0) red[wid] = sum;
    __syncthreads();
    sum = 0.f;
#pragma unroll
    for (int i = 0; i < 8; i++) sum += red[i];
    float inv = 1.f / sum;

    bf16* ph = Ph + row * T_;
    bf16* pl = Pl + row * T_;
#pragma unroll
    for (int i = 0; i < 2; i++) {
        uint2 hv, lv;
        bf16 h0, l0, h1, l1, h2, l2, h3, l3;
        split2(v[i * 4 + 0] * inv, h0, l0); split2(v[i * 4 + 1] * inv, h1, l1);
        split2(v[i * 4 + 2] * inv, h2, l2); split2(v[i * 4 + 3] * inv, h3, l3);
        hv.x = __bfloat16_as_ushort(h0) | ((uint32_t)__bfloat16_as_ushort(h1) << 16);
        hv.y = __bfloat16_as_ushort(h2) | ((uint32_t)__bfloat16_as_ushort(h3) << 16);
        lv.x = __bfloat16_as_ushort(l0) | ((uint32_t)__bfloat16_as_ushort(l1) << 16);
        lv.y = __bfloat16_as_ushort(l2) | ((uint32_t)__bfloat16_as_ushort(l3) << 16);
        reinterpret_cast<uint2*>(ph)[tid + i * 256] = hv;
        reinterpret_cast<uint2*>(pl)[tid + i * 256] = lv;
    }
}

// ---------------------------------------------------------------------------
extern "C" void kernel_launch(void* const* d_in, const int* in_sizes, int n_in,
                              void* d_out, int out_size)
{
    const float* x  = (const float*)d_in[0];
    const float* Wq = (const float*)d_in[1];
    const float* Wk = (const float*)d_in[2];
    const float* Wv = (const float*)d_in[3];
    const float* Wo = (const float*)d_in[4];
    const float* bo = (const float*)d_in[5];
    float* out = (float*)d_out;

    bf16 *xh, *xl, *Wqh, *Wql, *Wkh, *Wkl, *Wvh, *Wvl, *Woh, *Wol;
    bf16 *Qh, *Ql, *Kh, *Kl, *Vth, *Vtl, *Ph, *Pl, *Ah, *Al;
    float* S;
    cudaGetSymbolAddress((void**)&xh,  g_xh);  cudaGetSymbolAddress((void**)&xl,  g_xl);
    cudaGetSymbolAddress((void**)&Wqh, g_Wqh); cudaGetSymbolAddress((void**)&Wql, g_Wql);
    cudaGetSymbolAddress((void**)&Wkh, g_Wkh); cudaGetSymbolAddress((void**)&Wkl, g_Wkl);
    cudaGetSymbolAddress((void**)&Wvh, g_Wvh); cudaGetSymbolAddress((void**)&Wvl, g_Wvl);
    cudaGetSymbolAddress((void**)&Woh, g_Woh); cudaGetSymbolAddress((void**)&Wol, g_Wol);
    cudaGetSymbolAddress((void**)&Qh,  g_Qh);  cudaGetSymbolAddress((void**)&Ql,  g_Ql);
    cudaGetSymbolAddress((void**)&Kh,  g_Kh);  cudaGetSymbolAddress((void**)&Kl,  g_Kl);
    cudaGetSymbolAddress((void**)&Vth, g_Vth); cudaGetSymbolAddress((void**)&Vtl, g_Vtl);
    cudaGetSymbolAddress((void**)&Ph,  g_Ph);  cudaGetSymbolAddress((void**)&Pl,  g_Pl);
    cudaGetSymbolAddress((void**)&Ah,  g_Ah);  cudaGetSymbolAddress((void**)&Al,  g_Al);
    cudaGetSymbolAddress((void**)&S,   g_S);

    // stage bytes: 2*10240 + 2*BN*80 ; double-buffered
    const int SM128 = 2 * (2 * 10240 + 2 * 128 * 80);  // 81920
    const int SM64  = 2 * (2 * 10240 + 2 * 64 * 80);   // 61440
    cudaFuncSetAttribute(gemm_mma<128, 0>, cudaFuncAttributeMaxDynamicSharedMemorySize, SM128);
    cudaFuncSetAttribute(gemm_mma<128, 1>, cudaFuncAttributeMaxDynamicSharedMemorySize, SM128);
    cudaFuncSetAttribute(gemm_mma<64, 1>,  cudaFuncAttributeMaxDynamicSharedMemorySize, SM64);

    dim3 tb(32, 8);
    tsplit_kernel<<<dim3(E_ / 32,   E_ / 32), tb>>>(Wq, Wqh, Wql, E_, E_);
    tsplit_kernel<<<dim3(KVD_ / 32, E_ / 32), tb>>>(Wk, Wkh, Wkl, E_, KVD_);
    tsplit_kernel<<<dim3(KVD_ / 32, E_ / 32), tb>>>(Wv, Wvh, Wvl, E_, KVD_);
    tsplit_kernel<<<dim3(E_ / 32,   E_ / 32), tb>>>(Wo, Woh, Wol, E_, E_);
    split_kernel<<<(size_t)M_ * E_ / 4 / 256, 256>>>(x, xh, xl);

    // Q = x @ Wq (scaled 1/8) -> split bf16
    gemm_mma<128, 1><<<dim3(E_ / 128, M_ / 128, 1), 256, SM128>>>(
        xh, xl, Wqh, Wql, E_, E_, 64, 0, 0, 0, 0, 0, 0,
        nullptr, nullptr, Qh, Ql, E_, 0.125f);
    // K = x @ Wk -> split
    gemm_mma<128, 1><<<dim3(KVD_ / 128, M_ / 128, 1), 256, SM128>>>(
        xh, xl, Wkh, Wkl, E_, E_, 64, 0, 0, 0, 0, 0, 0,
        nullptr, nullptr, Kh, Kl, KVD_, 1.0f);
    // V^T[d][t] = sum_e Wv^T[d][e] * x[t][e] -> split [512 x 4096]
    gemm_mma<128, 1><<<dim3(M_ / 128, KVD_ / 128, 1), 256, SM128>>>(
        Wvh, Wvl, xh, xl, E_, E_, 64, 0, 0, 0, 0, 0, 0,
        nullptr, nullptr, Vth, Vtl, M_, 1.0f);

    // S[h] = Q_h @ K_h^T  (fp32), z = b*32+hq, K=64 -> nk=2
    gemm_mma<128, 0><<<dim3(T_ / 128, T_ / 128, NH_), 256, SM128>>>(
        Qh, Ql, Kh, Kl, E_, KVD_, 2,
        (long long)T_ * E_, 64,
        (long long)T_ * KVD_, 64,
        32LL * T_ * T_, (long long)T_ * T_,
        S, nullptr, nullptr, nullptr, T_, 1.0f);

    softmax_kernel<<<NH_ * T_, 256>>>(S, Ph, Pl);

    // O[h] = P_h @ V_h (V^T rows as B), K=2048 -> nk=64
    gemm_mma<64, 1><<<dim3(1, T_ / 128, NH_), 256, SM64>>>(
        Ph, Pl, Vth, Vtl, T_, M_, 64,
        32LL * T_ * T_, (long long)T_ * T_,
        (long long)T_, 64LL * M_,
        (long long)T_ * E_, 64,
        nullptr, nullptr, Ah, Al, E_, 1.0f);

    // out = A @ Wo + bo
    gemm_mma<128, 0><<<dim3(E_ / 128, M_ / 128, 1), 256, SM128>>>(
        Ah, Al, Woh, Wol, E_, E_, 64, 0, 0, 0, 0, 0, 0,
        out, bo, nullptr, nullptr, E_, 1.0f);
}

// round 7
// speedup vs baseline: 3.4693x; 1.3088x over previous
#include <cuda_runtime.h>
#include <cuda_bf16.h>
#include <math.h>
#include <stdint.h>

#define B_   2
#define T_   2048
#define E_   2048
#define HQ_  32
#define HKV_ 8
#define HD_  64
#define KVD_ 512
#define M_   4096

typedef __nv_bfloat16 bf16;

// ---------------------------------------------------------------------------
// Device scratch
// ---------------------------------------------------------------------------
__device__ bf16 g_xh[(size_t)M_*E_],   g_xl[(size_t)M_*E_];
__device__ bf16 g_Wqh[(size_t)E_*E_],  g_Wql[(size_t)E_*E_];
__device__ bf16 g_Wkh[(size_t)KVD_*E_],g_Wkl[(size_t)KVD_*E_];
__device__ bf16 g_Wvh[(size_t)KVD_*E_],g_Wvl[(size_t)KVD_*E_];
__device__ bf16 g_Woh[(size_t)E_*E_],  g_Wol[(size_t)E_*E_];
__device__ bf16 g_Qh[(size_t)M_*E_],   g_Ql[(size_t)M_*E_];      // Q*0.125
__device__ bf16 g_Kh[(size_t)M_*KVD_], g_Kl[(size_t)M_*KVD_];
__device__ bf16 g_Vth[(size_t)KVD_*M_],g_Vtl[(size_t)KVD_*M_];   // V^T [512,4096]
__device__ bf16 g_Ah[(size_t)M_*E_],   g_Al[(size_t)M_*E_];

// ---------------------------------------------------------------------------
// Helpers
// ---------------------------------------------------------------------------
__device__ __forceinline__ uint32_t smem_u32(const void* p) {
    return (uint32_t)__cvta_generic_to_shared(p);
}
#define CP_ASYNC16(sa, ga) \
    asm volatile("cp.async.cg.shared.global [%0], [%1], 16;" :: "r"(sa), "l"(ga))
#define CP_COMMIT() asm volatile("cp.async.commit_group;" ::: "memory")
#define CP_WAIT0()  asm volatile("cp.async.wait_group 0;" ::: "memory")
#define CP_WAIT1()  asm volatile("cp.async.wait_group 1;" ::: "memory")

__device__ __forceinline__ void ldm_x4(uint32_t* r, uint32_t addr) {
    asm volatile("ldmatrix.sync.aligned.m8n8.x4.shared.b16 {%0,%1,%2,%3}, [%4];"
        : "=r"(r[0]), "=r"(r[1]), "=r"(r[2]), "=r"(r[3]) : "r"(addr));
}
__device__ __forceinline__ void ldm_x2(uint32_t* r, uint32_t addr) {
    asm volatile("ldmatrix.sync.aligned.m8n8.x2.shared.b16 {%0,%1}, [%2];"
        : "=r"(r[0]), "=r"(r[1]) : "r"(addr));
}
__device__ __forceinline__ void mma16816(float* c, const uint32_t* a, const uint32_t* b) {
    asm volatile("mma.sync.aligned.m16n8k16.row.col.f32.bf16.bf16.f32 "
        "{%0,%1,%2,%3}, {%4,%5,%6,%7}, {%8,%9}, {%0,%1,%2,%3};"
        : "+f"(c[0]), "+f"(c[1]), "+f"(c[2]), "+f"(c[3])
        : "r"(a[0]), "r"(a[1]), "r"(a[2]), "r"(a[3]), "r"(b[0]), "r"(b[1]));
}
__device__ __forceinline__ void split2(float v, bf16& h, bf16& l) {
    h = __float2bfloat16(v);
    l = __float2bfloat16(v - __bfloat162float(h));
}
__device__ __forceinline__ void split_pack(float a, float b, uint32_t& hp, uint32_t& lp) {
    bf16 ha, la, hb, lb;
    split2(a, ha, la); split2(b, hb, lb);
    hp = (uint32_t)__bfloat16_as_ushort(ha) | ((uint32_t)__bfloat16_as_ushort(hb) << 16);
    lp = (uint32_t)__bfloat16_as_ushort(la) | ((uint32_t)__bfloat16_as_ushort(lb) << 16);
}

// Stage loader for gemm_mma: ROWS x 32 bf16 tile -> SMEM rows padded to 80B
template<int ROWS>
__device__ __forceinline__ void stage_load(uint32_t sdst, const bf16* __restrict__ g,
                                           int ld, int tid) {
#pragma unroll
    for (int i = 0; i < ROWS / 64; i++) {
        int idx = tid + i * 256;
        int r = idx >> 2, q = idx & 3;
        CP_ASYNC16(sdst + r * 80 + q * 16, g + (size_t)r * ld + q * 8);
    }
}

// ---------------------------------------------------------------------------
// Warp-MMA GEMM, hi/lo bf16 split (3 HMMA per product term). (as in R5)
// ---------------------------------------------------------------------------
template<int BN, int OUT>
__global__ __launch_bounds__(256) void gemm_mma(
    const bf16* __restrict__ Ah_, const bf16* __restrict__ Al_,
    const bf16* __restrict__ Bh_, const bf16* __restrict__ Bl_,
    int lda, int ldb, int nk,
    float* Cf, const float* bias, bf16* Ch, bf16* Cl, int ldc, float scale)
{
    extern __shared__ char smem[];
    const uint32_t sb = smem_u32(smem);
    const int tid = threadIdx.x, wid = tid >> 5, lane = tid & 31;
    const int wm = wid & 1, wn = wid >> 1;
    constexpr int WN = BN / 4;
    constexpr int NT = WN / 8;
    constexpr int ATB = 128 * 80;
    constexpr int BTB = BN * 80;
    constexpr int STG = 2 * ATB + 2 * BTB;

    const int row0 = blockIdx.y * 128;
    const int col0 = blockIdx.x * BN;

    const bf16* gAh = Ah_ + (size_t)row0 * lda;
    const bf16* gAl = Al_ + (size_t)row0 * lda;
    const bf16* gBh = Bh_ + (size_t)col0 * ldb;
    const bf16* gBl = Bl_ + (size_t)col0 * ldb;

    float acc[4][NT][4];
#pragma unroll
    for (int i = 0; i < 4; i++)
#pragma unroll
        for (int j = 0; j < NT; j++)
#pragma unroll
            for (int c = 0; c < 4; c++) acc[i][j][c] = 0.f;

    stage_load<128>(sb,                 gAh, lda, tid);
    stage_load<128>(sb + ATB,           gAl, lda, tid);
    stage_load<BN >(sb + 2 * ATB,       gBh, ldb, tid);
    stage_load<BN >(sb + 2 * ATB + BTB, gBl, ldb, tid);
    CP_COMMIT();

    const uint32_t aRow = (uint32_t)(wm * 64 + (lane & 15)) * 80 + (lane >> 4) * 16;
    const uint32_t bRow = (uint32_t)(wn * WN + (lane & 7)) * 80 + ((lane >> 3) & 1) * 16;

    for (int kt = 0; kt < nk; kt++) {
        const int cur = kt & 1;
        if (kt + 1 < nk) {
            const uint32_t sn = sb + ((kt + 1) & 1) * STG;
            stage_load<128>(sn,                 gAh + (kt + 1) * 32, lda, tid);
            stage_load<128>(sn + ATB,           gAl + (kt + 1) * 32, lda, tid);
            stage_load<BN >(sn + 2 * ATB,       gBh + (kt + 1) * 32, ldb, tid);
            stage_load<BN >(sn + 2 * ATB + BTB, gBl + (kt + 1) * 32, ldb, tid);
            CP_COMMIT();
            CP_WAIT1();
        } else {
            CP_WAIT0();
        }
        __syncthreads();

        const uint32_t sa = sb + cur * STG + aRow;
        const uint32_t sbv = sb + cur * STG + 2 * ATB + bRow;
#pragma unroll
        for (int ks = 0; ks < 2; ks++) {
            uint32_t ah[4][4], al[4][4], bh[NT][2], bl[NT][2];
#pragma unroll
            for (int mt = 0; mt < 4; mt++) {
                ldm_x4(ah[mt], sa + mt * 16 * 80 + ks * 32);
                ldm_x4(al[mt], sa + ATB + mt * 16 * 80 + ks * 32);
            }
#pragma unroll
            for (int nt = 0; nt < NT; nt++) {
                ldm_x2(bh[nt], sbv + nt * 8 * 80 + ks * 32);
                ldm_x2(bl[nt], sbv + BTB + nt * 8 * 80 + ks * 32);
            }
#pragma unroll
            for (int mt = 0; mt < 4; mt++)
#pragma unroll
                for (int nt = 0; nt < NT; nt++) {
                    mma16816(acc[mt][nt], ah[mt], bh[nt]);
                    mma16816(acc[mt][nt], ah[mt], bl[nt]);
                    mma16816(acc[mt][nt], al[mt], bh[nt]);
                }
        }
        __syncthreads();
    }

    const int rw = lane >> 2, cw = (lane & 3) * 2;
#pragma unroll
    for (int mt = 0; mt < 4; mt++) {
#pragma unroll
        for (int nt = 0; nt < NT; nt++) {
            const int rg = row0 + wm * 64 + mt * 16 + rw;
            const int cg = col0 + wn * WN + nt * 8 + cw;
            float v0 = acc[mt][nt][0], v1 = acc[mt][nt][1];
            float v2 = acc[mt][nt][2], v3 = acc[mt][nt][3];
            if (OUT == 0) {
                float b0 = 0.f, b1 = 0.f;
                if (bias) { b0 = bias[cg]; b1 = bias[cg + 1]; }
                *reinterpret_cast<float2*>(Cf + (size_t)rg * ldc + cg) =
                    make_float2(v0 + b0, v1 + b1);
                *reinterpret_cast<float2*>(Cf + (size_t)(rg + 8) * ldc + cg) =
                    make_float2(v2 + b0, v3 + b1);
            } else {
                uint32_t h0, l0, h1, l1;
                split_pack(v0 * scale, v1 * scale, h0, l0);
                split_pack(v2 * scale, v3 * scale, h1, l1);
                size_t i0 = (size_t)rg * ldc + cg;
                size_t i1 = (size_t)(rg + 8) * ldc + cg;
                *reinterpret_cast<uint32_t*>(Ch + i0) = h0;
                *reinterpret_cast<uint32_t*>(Cl + i0) = l0;
                *reinterpret_cast<uint32_t*>(Ch + i1) = h1;
                *reinterpret_cast<uint32_t*>(Cl + i1) = l1;
            }
        }
    }
}

// ---------------------------------------------------------------------------
// Fused flash attention (bf16 hi/lo on tensor pipe, fp32 online softmax).
// CTA = 128 queries x 1 query head. 8 warps x 16 rows. KV tiles of 128.
// ---------------------------------------------------------------------------
#define KROW 144
#define VROW 272
#define KTB (128 * KROW)   // 18432
#define VTB (64 * VROW)    // 17408
#define FSTG (2 * KTB + 2 * VTB)  // 71680

__device__ __forceinline__ void kv_load(uint32_t dst,
    const bf16* __restrict__ gKh, const bf16* __restrict__ gKl,
    const bf16* __restrict__ gVh, const bf16* __restrict__ gVl,
    int kt, int tid)
{
#pragma unroll
    for (int i = 0; i < 4; i++) {
        int idx = tid + i * 256;
        int r = idx >> 3, q = idx & 7;
        size_t src = (size_t)(kt * 128 + r) * KVD_ + q * 8;
        CP_ASYNC16(dst + r * KROW + q * 16, gKh + src);
        CP_ASYNC16(dst + KTB + r * KROW + q * 16, gKl + src);
    }
#pragma unroll
    for (int i = 0; i < 4; i++) {
        int idx = tid + i * 256;
        int r = idx >> 4, q = idx & 15;
        size_t src = (size_t)r * M_ + kt * 128 + q * 8;
        CP_ASYNC16(dst + 2 * KTB + r * VROW + q * 16, gVh + src);
        CP_ASYNC16(dst + 2 * KTB + VTB + r * VROW + q * 16, gVl + src);
    }
}

__global__ __launch_bounds__(256) void flash_attn(
    const bf16* __restrict__ Qh_, const bf16* __restrict__ Ql_,
    const bf16* __restrict__ Kh_, const bf16* __restrict__ Kl_,
    const bf16* __restrict__ Vh_, const bf16* __restrict__ Vl_,
    bf16* __restrict__ Ah, bf16* __restrict__ Al)
{
    extern __shared__ char smem[];
    const uint32_t sb = smem_u32(smem);
    const int tid = threadIdx.x, wid = tid >> 5, lane = tid & 31;
    const int q0 = blockIdx.x * 128, hq = blockIdx.y, b = blockIdx.z;
    const int hkv = hq >> 2;

    const bf16* gQh = Qh_ + (size_t)(b * T_ + q0) * E_ + hq * HD_;
    const bf16* gQl = Ql_ + (size_t)(b * T_ + q0) * E_ + hq * HD_;
    const bf16* gKh = Kh_ + (size_t)(b * T_) * KVD_ + hkv * HD_;
    const bf16* gKl = Kl_ + (size_t)(b * T_) * KVD_ + hkv * HD_;
    const bf16* gVh = Vh_ + (size_t)(hkv * HD_) * M_ + b * T_;
    const bf16* gVl = Vl_ + (size_t)(hkv * HD_) * M_ + b * T_;

    // Q -> stage-1 region (temporary), then fragments to registers
#pragma unroll
    for (int i = 0; i < 4; i++) {
        int idx = tid + i * 256, r = idx >> 3, q = idx & 7;
        size_t src = (size_t)r * E_ + q * 8;
        CP_ASYNC16(sb + FSTG + r * KROW + q * 16, gQh + src);
        CP_ASYNC16(sb + FSTG + KTB + r * KROW + q * 16, gQl + src);
    }
    CP_COMMIT();
    kv_load(sb, gKh, gKl, gVh, gVl, 0, tid);
    CP_COMMIT();
    CP_WAIT1();
    __syncthreads();

    uint32_t qh[4][4], ql[4][4];
    {
        uint32_t qb = sb + FSTG + (uint32_t)(wid * 16 + (lane & 15)) * KROW
                    + (lane >> 4) * 16;
#pragma unroll
        for (int ks = 0; ks < 4; ks++) {
            ldm_x4(qh[ks], qb + ks * 32);
            ldm_x4(ql[ks], qb + KTB + ks * 32);
        }
    }
    __syncthreads();  // all warps done with Q staging before tile-1 prefetch

    float o[8][4];
#pragma unroll
    for (int j = 0; j < 8; j++)
#pragma unroll
        for (int c = 0; c < 4; c++) o[j][c] = 0.f;
    float m0 = -INFINITY, m1 = -INFINITY, l0 = 0.f, l1 = 0.f;

    for (int kt = 0; kt < 16; kt++) {
        const uint32_t cur = sb + (kt & 1) * FSTG;
        if (kt < 15) {
            kv_load(sb + ((kt + 1) & 1) * FSTG, gKh, gKl, gVh, gVl, kt + 1, tid);
            CP_COMMIT();
            CP_WAIT1();
        } else {
            CP_WAIT0();
        }
        __syncthreads();

        // ---- S = Q K^T (fp32 accum, 3 HMMA hi/lo) ----
        float s[16][4];
#pragma unroll
        for (int j = 0; j < 16; j++)
#pragma unroll
            for (int c = 0; c < 4; c++) s[j][c] = 0.f;

        const uint32_t kb = cur + (lane & 7) * KROW + ((lane >> 3) & 1) * 16;
#pragma unroll
        for (int j = 0; j < 16; j++) {
#pragma unroll
            for (int ks = 0; ks < 4; ks++) {
                uint32_t bh[2], bl[2];
                ldm_x2(bh, kb + j * (8 * KROW) + ks * 32);
                ldm_x2(bl, kb + KTB + j * (8 * KROW) + ks * 32);
                mma16816(s[j], qh[ks], bh);
                mma16816(s[j], ql[ks], bh);
                mma16816(s[j], qh[ks], bl);
            }
        }

        // ---- online softmax (rows rw and rw+8; quad = 4 lanes per row) ----
        float mx0 = -INFINITY, mx1 = -INFINITY;
#pragma unroll
        for (int j = 0; j < 16; j++) {
            mx0 = fmaxf(mx0, fmaxf(s[j][0], s[j][1]));
            mx1 = fmaxf(mx1, fmaxf(s[j][2], s[j][3]));
        }
        mx0 = fmaxf(mx0, __shfl_xor_sync(~0u, mx0, 1));
        mx0 = fmaxf(mx0, __shfl_xor_sync(~0u, mx0, 2));
        mx1 = fmaxf(mx1, __shfl_xor_sync(~0u, mx1, 1));
        mx1 = fmaxf(mx1, __shfl_xor_sync(~0u, mx1, 2));
        const float nm0 = fmaxf(m0, mx0), nm1 = fmaxf(m1, mx1);
        const float corr0 = __expf(m0 - nm0), corr1 = __expf(m1 - nm1);
        float rs0 = 0.f, rs1 = 0.f;
#pragma unroll
        for (int j = 0; j < 16; j++) {
            s[j][0] = __expf(s[j][0] - nm0);
            s[j][1] = __expf(s[j][1] - nm0);
            s[j][2] = __expf(s[j][2] - nm1);
            s[j][3] = __expf(s[j][3] - nm1);
            rs0 += s[j][0] + s[j][1];
            rs1 += s[j][2] + s[j][3];
        }
        rs0 += __shfl_xor_sync(~0u, rs0, 1);
        rs0 += __shfl_xor_sync(~0u, rs0, 2);
        rs1 += __shfl_xor_sync(~0u, rs1, 1);
        rs1 += __shfl_xor_sync(~0u, rs1, 2);
        l0 = l0 * corr0 + rs0;
        l1 = l1 * corr1 + rs1;
        m0 = nm0; m1 = nm1;
#pragma unroll
        for (int j = 0; j < 8; j++) {
            o[j][0] *= corr0; o[j][1] *= corr0;
            o[j][2] *= corr1; o[j][3] *= corr1;
        }

        // ---- O += P V  (P fragments built in-register from S accumulators) ----
        const uint32_t vb = cur + 2 * KTB + (lane & 7) * VROW + ((lane >> 3) & 1) * 16;
#pragma unroll
        for (int ks = 0; ks < 8; ks++) {
            uint32_t ph[4], pl[4];
            split_pack(s[2 * ks][0],     s[2 * ks][1],     ph[0], pl[0]);
            split_pack(s[2 * ks][2],     s[2 * ks][3],     ph[1], pl[1]);
            split_pack(s[2 * ks + 1][0], s[2 * ks + 1][1], ph[2], pl[2]);
            split_pack(s[2 * ks + 1][2], s[2 * ks + 1][3], ph[3], pl[3]);
#pragma unroll
            for (int j = 0; j < 8; j++) {
                uint32_t vh[2], vl[2];
                ldm_x2(vh, vb + j * (8 * VROW) + ks * 32);
                ldm_x2(vl, vb + VTB + j * (8 * VROW) + ks * 32);
                mma16816(o[j], ph, vh);
                mma16816(o[j], ph, vl);
                mma16816(o[j], pl, vh);
            }
        }
        __syncthreads();
    }

    // ---- epilogue: normalize, split hi/lo, store ----
    const float inv0 = 1.f / l0, inv1 = 1.f / l1;
    const int r0 = b * T_ + q0 + wid * 16 + (lane >> 2);
    const int cb = hq * HD_ + (lane & 3) * 2;
#pragma unroll
    for (int j = 0; j < 8; j++) {
        uint32_t h0, lo0, h1, lo1;
        split_pack(o[j][0] * inv0, o[j][1] * inv0, h0, lo0);
        split_pack(o[j][2] * inv1, o[j][3] * inv1, h1, lo1);
        size_t i0 = (size_t)r0 * E_ + cb + 8 * j;
        size_t i1 = (size_t)(r0 + 8) * E_ + cb + 8 * j;
        *reinterpret_cast<uint32_t*>(Ah + i0) = h0;
        *reinterpret_cast<uint32_t*>(Al + i0) = lo0;
        *reinterpret_cast<uint32_t*>(Ah + i1) = h1;
        *reinterpret_cast<uint32_t*>(Al + i1) = lo1;
    }
}

// ---------------------------------------------------------------------------
// Prep kernels
// ---------------------------------------------------------------------------
__global__ void tsplit_kernel(const float* __restrict__ W, bf16* __restrict__ Th,
                              bf16* __restrict__ Tl, int K, int N)
{
    __shared__ float s[32][33];
    int n0 = blockIdx.x * 32, k0 = blockIdx.y * 32;
    int tx = threadIdx.x, ty = threadIdx.y;
#pragma unroll
    for (int i = ty; i < 32; i += 8)
        s[i][tx] = W[(size_t)(k0 + i) * N + n0 + tx];
    __syncthreads();
#pragma unroll
    for (int i = ty; i < 32; i += 8) {
        float v = s[tx][i];
        bf16 h, l; split2(v, h, l);
        Th[(size_t)(n0 + i) * K + k0 + tx] = h;
        Tl[(size_t)(n0 + i) * K + k0 + tx] = l;
    }
}

__global__ void split_kernel(const float* __restrict__ x, bf16* __restrict__ xh,
                             bf16* __restrict__ xl)
{
    size_t i = (size_t)blockIdx.x * blockDim.x + threadIdx.x;
    float4 v = reinterpret_cast<const float4*>(x)[i];
    uint32_t h0, l0, h1, l1;
    split_pack(v.x, v.y, h0, l0);
    split_pack(v.z, v.w, h1, l1);
    reinterpret_cast<uint2*>(xh)[i] = make_uint2(h0, h1);
    reinterpret_cast<uint2*>(xl)[i] = make_uint2(l0, l1);
}

// ---------------------------------------------------------------------------
extern "C" void kernel_launch(void* const* d_in, const int* in_sizes, int n_in,
                              void* d_out, int out_size)
{
    const float* x  = (const float*)d_in[0];
    const float* Wq = (const float*)d_in[1];
    const float* Wk = (const float*)d_in[2];
    const float* Wv = (const float*)d_in[3];
    const float* Wo = (const float*)d_in[4];
    const float* bo = (const float*)d_in[5];
    float* out = (float*)d_out;

    bf16 *xh, *xl, *Wqh, *Wql, *Wkh, *Wkl, *Wvh, *Wvl, *Woh, *Wol;
    bf16 *Qh, *Ql, *Kh, *Kl, *Vth, *Vtl, *Ah, *Al;
    cudaGetSymbolAddress((void**)&xh,  g_xh);  cudaGetSymbolAddress((void**)&xl,  g_xl);
    cudaGetSymbolAddress((void**)&Wqh, g_Wqh); cudaGetSymbolAddress((void**)&Wql, g_Wql);
    cudaGetSymbolAddress((void**)&Wkh, g_Wkh); cudaGetSymbolAddress((void**)&Wkl, g_Wkl);
    cudaGetSymbolAddress((void**)&Wvh, g_Wvh); cudaGetSymbolAddress((void**)&Wvl, g_Wvl);
    cudaGetSymbolAddress((void**)&Woh, g_Woh); cudaGetSymbolAddress((void**)&Wol, g_Wol);
    cudaGetSymbolAddress((void**)&Qh,  g_Qh);  cudaGetSymbolAddress((void**)&Ql,  g_Ql);
    cudaGetSymbolAddress((void**)&Kh,  g_Kh);  cudaGetSymbolAddress((void**)&Kl,  g_Kl);
    cudaGetSymbolAddress((void**)&Vth, g_Vth); cudaGetSymbolAddress((void**)&Vtl, g_Vtl);
    cudaGetSymbolAddress((void**)&Ah,  g_Ah);  cudaGetSymbolAddress((void**)&Al,  g_Al);

    const int SM128 = 2 * (2 * 10240 + 2 * 128 * 80);  // 81920
    const int SMF   = 2 * FSTG;                         // 143360
    cudaFuncSetAttribute(gemm_mma<128, 0>, cudaFuncAttributeMaxDynamicSharedMemorySize, SM128);
    cudaFuncSetAttribute(gemm_mma<128, 1>, cudaFuncAttributeMaxDynamicSharedMemorySize, SM128);
    cudaFuncSetAttribute(flash_attn, cudaFuncAttributeMaxDynamicSharedMemorySize, SMF);

    dim3 tb(32, 8);
    tsplit_kernel<<<dim3(E_ / 32,   E_ / 32), tb>>>(Wq, Wqh, Wql, E_, E_);
    tsplit_kernel<<<dim3(KVD_ / 32, E_ / 32), tb>>>(Wk, Wkh, Wkl, E_, KVD_);
    tsplit_kernel<<<dim3(KVD_ / 32, E_ / 32), tb>>>(Wv, Wvh, Wvl, E_, KVD_);
    tsplit_kernel<<<dim3(E_ / 32,   E_ / 32), tb>>>(Wo, Woh, Wol, E_, E_);
    split_kernel<<<(size_t)M_ * E_ / 4 / 256, 256>>>(x, xh, xl);

    // Q = x @ Wq (scaled 1/8) -> split bf16
    gemm_mma<128, 1><<<dim3(E_ / 128, M_ / 128), 256, SM128>>>(
        xh, xl, Wqh, Wql, E_, E_, 64, nullptr, nullptr, Qh, Ql, E_, 0.125f);
    // K = x @ Wk -> split
    gemm_mma<128, 1><<<dim3(KVD_ / 128, M_ / 128), 256, SM128>>>(
        xh, xl, Wkh, Wkl, E_, E_, 64, nullptr, nullptr, Kh, Kl, KVD_, 1.0f);
    // V^T[d][t] = sum_e Wv^T[d][e] * x[t][e] -> split [512 x 4096]
    gemm_mma<128, 1><<<dim3(M_ / 128, KVD_ / 128), 256, SM128>>>(
        Wvh, Wvl, xh, xl, E_, E_, 64, nullptr, nullptr, Vth, Vtl, M_, 1.0f);

    // fused attention -> Ah/Al
    flash_attn<<<dim3(T_ / 128, HQ_, B_), 256, SMF>>>(
        Qh, Ql, Kh, Kl, Vth, Vtl, Ah, Al);

    // out = A @ Wo + bo
    gemm_mma<128, 0><<<dim3(E_ / 128, M_ / 128), 256, SM128>>>(
        Ah, Al, Woh, Wol, E_, E_, 64, out, bo, nullptr, nullptr, E_, 1.0f);
}